// round 16
// baseline (speedup 1.0000x reference)
#include <cuda_runtime.h>
#include <cstdint>
#include <math.h>

#define NB 8
#define THREADS 256
#define FEAT 128
#define SEQ 32
#define NHEAD 4
#define HDIM 32
#define LN_EPS 1e-5f
#define INV_SQRT_D 0.17677669529663687f

// dynamic smem layout (float offsets)
#define OFF_Q    0            // NB*128 query rows; reused as out rows (Phase F+)
#define OFF_QP   1024         // NB*128 qp; reused as attn [j][s*4+h]; reused as wv (Phase E)
#define OFF_T    2048         // NB*4*128 t vectors
#define OFF_U    6144         // NB*4*128 aggregated values
#define OFF_KB0  10240        // 31*132=4092 (pad 4096): key buffer stage 0
#define OFF_VB0  14336        // 32*132=4224: value buffer stage 0
#define OFF_KB1  18560        // 4096: key buffer stage 1
#define OFF_VB1  22656        // 4224: value buffer stage 1; also Wk stage [128][33] in Phase B
#define OFF_SB   26880        // NB*4 score bias
#define OFF_MI   26912        // NB mask values
#define SMEM_FLOATS 26920     // 107680 B -> 2 CTAs/SM, 16 warps/SM

__device__ __forceinline__ float warp_max(float v) {
#pragma unroll
    for (int o = 16; o; o >>= 1) v = fmaxf(v, __shfl_xor_sync(0xffffffffu, v, o));
    return v;
}
__device__ __forceinline__ float warp_sum(float v) {
#pragma unroll
    for (int o = 16; o; o >>= 1) v += __shfl_xor_sync(0xffffffffu, v, o);
    return v;
}

// async-stage `rows` rows of a [SEQ, N, FEAT] tensor for node n into smem (stride 33 float4)
__device__ __forceinline__ void prefetch_rows(const float4* __restrict__ src4,
                                              uint32_t dst_smem_addr,
                                              int n, int rows, int N, int tid) {
    for (int r = tid; r < rows * 32; r += THREADS) {
        int s = r >> 5, k = r & 31;
        uint32_t dst = dst_smem_addr + (uint32_t)(s * 33 + k) * 16u;
        const float4* src = src4 + ((size_t)s * N + n) * 32 + k;
        asm volatile("cp.async.cg.shared.global [%0], [%1], 16;" :: "r"(dst), "l"(src));
    }
}

__global__ __launch_bounds__(THREADS)
void mha_fused_kernel(
    const float* __restrict__ query, const float* __restrict__ key,
    const float* __restrict__ value, const int* __restrict__ mask_idx,
    const float* __restrict__ Wq, const float* __restrict__ bq,
    const float* __restrict__ Wk, const float* __restrict__ bk,
    const float* __restrict__ Wv, const float* __restrict__ bv,
    const float* __restrict__ Wo, const float* __restrict__ bo,
    const float* __restrict__ gamma, const float* __restrict__ beta,
    float* __restrict__ out, int N)
{
    extern __shared__ float sm[];
    const int tid  = threadIdx.x;
    const int w    = tid >> 5;       // warp id (0..7)
    const int lane = tid & 31;
    const int fo   = tid & 127;      // feature index for GEMM phases
    const int half = tid >> 7;       // node-half (0/1) for GEMM phases
    const int n0   = blockIdx.x * NB;

    float* s_q    = sm + OFF_Q;
    float* s_qp   = sm + OFF_QP;     // -> attn -> wv
    float* s_t    = sm + OFF_T;
    float* s_u    = sm + OFF_U;
    float* s_sb   = sm + OFF_SB;
    int*   s_mi   = (int*)(sm + OFF_MI);
    float* s_attn = s_qp;            // overlay (qp dead after sbias)
    float* s_wk   = sm + OFF_VB1;    // Wk staging (buffer 1 is free during Phase B)

    const uint32_t kb_addr[2] = { (uint32_t)__cvta_generic_to_shared(sm + OFF_KB0),
                                  (uint32_t)__cvta_generic_to_shared(sm + OFF_KB1) };
    const uint32_t vb_addr[2] = { (uint32_t)__cvta_generic_to_shared(sm + OFF_VB0),
                                  (uint32_t)__cvta_generic_to_shared(sm + OFF_VB1) };
    const float4* key4 = reinterpret_cast<const float4*>(key);
    const float4* val4 = reinterpret_cast<const float4*>(value);

    // ---- stage query rows + mask values ----
    for (int i = tid; i < NB * FEAT; i += THREADS) {
        int n = n0 + (i >> 7);
        s_q[i] = (n < N) ? query[(size_t)n * FEAT + (i & 127)] : 0.f;
    }
    if (tid < NB) {
        int n = n0 + tid;
        s_mi[tid] = (n < N) ? mask_idx[n] : 0;
    }
    __syncthreads();

    // ---- prologue: issue K[0]+V[0] into buffer 0 (overlaps Phases A/B) ----
    {
        if (n0 < N) {
            int m0 = s_mi[0];
            int Sa0 = (m0 == 0) ? SEQ : m0;
            if (m0 > 0) prefetch_rows(key4, kb_addr[0], n0, m0, N, tid);
            prefetch_rows(val4, vb_addr[0], n0, Sa0, N, tid);
        }
        asm volatile("cp.async.commit_group;");
    }

    // ---- Phase A: qp = q @ Wq + bq  (thread = (out-feature, node-half), 4 accumulators) ----
    {
        float acc[4];
        float b = bq[fo];
#pragma unroll
        for (int jj = 0; jj < 4; jj++) acc[jj] = b;
#pragma unroll 4
        for (int f = 0; f < FEAT; f++) {
            float wgt = Wq[f * FEAT + fo];
#pragma unroll
            for (int jj = 0; jj < 4; jj++)
                acc[jj] = fmaf(s_q[(half * 4 + jj) * FEAT + f], wgt, acc[jj]);
        }
#pragma unroll
        for (int jj = 0; jj < 4; jj++) s_qp[(half * 4 + jj) * FEAT + fo] = acc[jj];
    }
    __syncthreads();

    // ---- Phase B: t[j][h][f] = sum_d Wk[f, h*32+d] * qp[j, h*32+d] ----
    // Wk head chunk staged into buffer-1 V region (untouched by prologue prefetch).
    for (int h = 0; h < NHEAD; h++) {
        for (int r = tid; r < FEAT * HDIM; r += THREADS) {
            int f = r >> 5, dd = r & 31;
            s_wk[f * 33 + dd] = Wk[f * FEAT + h * HDIM + dd];
        }
        __syncthreads();
        float acc[4];
#pragma unroll
        for (int jj = 0; jj < 4; jj++) acc[jj] = 0.f;
#pragma unroll
        for (int dd = 0; dd < HDIM; dd++) {
            float wgt = s_wk[fo * 33 + dd];
#pragma unroll
            for (int jj = 0; jj < 4; jj++)
                acc[jj] = fmaf(s_qp[(half * 4 + jj) * FEAT + h * HDIM + dd], wgt, acc[jj]);
        }
#pragma unroll
        for (int jj = 0; jj < 4; jj++)
            s_t[(half * 4 + jj) * (NHEAD * FEAT) + h * FEAT + fo] = acc[jj];
        __syncthreads();
    }

    // ---- score bias: sbias[j][h] = qp_h . bk_h ----
    if (tid < NB * NHEAD) {
        int j = tid >> 2, h = tid & 3;
        float s = 0.f;
        for (int dd = 0; dd < HDIM; dd++)
            s += s_qp[j * FEAT + h * HDIM + dd] * bk[h * HDIM + dd];
        s_sb[tid] = s;
    }
    // s_sb visibility established by the first barrier inside the loop.

    // ---- Per-node double-buffered loop ----
    // iter j: wait(K,V)[j] | bar | issue (K,V)[j+1] -> other buf | scores[j] | bar | agg[j]
    for (int j = 0; j < NB; j++) {
        const int p = j & 1;
        int n = n0 + j;
        bool valid = (n < N);
        int midx = valid ? s_mi[j] : 0;
        // midx==0: reference adds -1e9 which absorbs all scores in fp32 -> uniform softmax.
        bool uniform = (midx == 0);
        int Sa = uniform ? SEQ : midx;     // rows for V aggregation

        // ---- wait for this node's K+V; fence prior-iteration smem writes ----
        asm volatile("cp.async.wait_group 0;" ::: "memory");
        __syncthreads();

        // ---- issue next node's K+V into the other buffer (covered by scores+agg) ----
        if (j + 1 < NB) {
            int n2 = n0 + j + 1;
            if (n2 < N) {
                int m2 = s_mi[j + 1];
                int Sa2 = (m2 == 0) ? SEQ : m2;
                if (m2 > 0) prefetch_rows(key4, kb_addr[1 - p], n2, m2, N, tid);
                prefetch_rows(val4, vb_addr[1 - p], n2, Sa2, N, tid);
            }
        }
        asm volatile("cp.async.commit_group;");

        // ---- scores + softmax (warps 0-3: warp = head, lane = seq pos) ----
        if (valid && w < NHEAD) {
            if (!uniform) {
                const float4* kb4 = reinterpret_cast<const float4*>(sm + (p ? OFF_KB1 : OFF_KB0));
                float sc = -1e30f;
                float pr = 0.f;
                if (lane < midx) {
                    const float4* t4 = reinterpret_cast<const float4*>(s_t + j * (NHEAD * FEAT) + w * FEAT);
                    float ax = 0.f, ay = 0.f, az = 0.f, aw = 0.f;
#pragma unroll 8
                    for (int k = 0; k < FEAT / 4; k++) {
                        float4 kv = kb4[lane * 33 + k];
                        float4 tv = t4[k];
                        ax = fmaf(kv.x, tv.x, ax);
                        ay = fmaf(kv.y, tv.y, ay);
                        az = fmaf(kv.z, tv.z, az);
                        aw = fmaf(kv.w, tv.w, aw);
                    }
                    sc = (((ax + ay) + (az + aw)) + s_sb[j * 4 + w]) * INV_SQRT_D;
                }
                float m = warp_max(sc);
                if (lane < midx) pr = expf(sc - m);
                float denom = warp_sum(pr);
                if (lane < midx) s_attn[j * FEAT + lane * 4 + w] = pr / denom;
            } else {
                s_attn[j * FEAT + lane * 4 + w] = 1.0f / SEQ;
            }
        }
        __syncthreads();   // attn visible to all

        // ---- u[j][h][f] = sum_{s<Sa} attn[s,h] * V_smem[s,f] ----
        // thread = (feature fo, head-pair half): heads 2*half, 2*half+1
        if (valid) {
            const float* vbp = sm + (p ? OFF_VB1 : OFF_VB0);
            const float* ab = s_attn + j * FEAT + half * 2;
            float a0 = 0.f, a1 = 0.f;
#pragma unroll 8
            for (int s = 0; s < Sa; s++) {
                float vv = vbp[s * 132 + fo];
                float2 av = *reinterpret_cast<const float2*>(ab + s * 4);
                a0 = fmaf(av.x, vv, a0);
                a1 = fmaf(av.y, vv, a1);
            }
            s_u[j * (NHEAD * FEAT) + (2 * half + 0) * FEAT + fo] = a0;
            s_u[j * (NHEAD * FEAT) + (2 * half + 1) * FEAT + fo] = a1;
        }
    }
    __syncthreads();

    // ---- Phase E: wv[j][o] = bv[o] + sum_f u[j][o/32][f] * Wv[f,o]  (into s_qp overlay) ----
    {
        float acc[4];
        float b = bv[fo];
#pragma unroll
        for (int jj = 0; jj < 4; jj++) acc[jj] = b;
        const int h = fo >> 5;
#pragma unroll 4
        for (int f = 0; f < FEAT; f++) {
            float wgt = Wv[f * FEAT + fo];
#pragma unroll
            for (int jj = 0; jj < 4; jj++)
                acc[jj] = fmaf(s_u[(half * 4 + jj) * (NHEAD * FEAT) + h * FEAT + f], wgt, acc[jj]);
        }
#pragma unroll
        for (int jj = 0; jj < 4; jj++) s_qp[(half * 4 + jj) * FEAT + fo] = acc[jj];   // wv
    }
    __syncthreads();

    // ---- Phase F: out[j][f'] = bo[f'] + sum_o wv[j][o] * Wo[o,f']  (into s_q overlay) ----
    {
        float acc[4];
        float b = bo[fo];
#pragma unroll
        for (int jj = 0; jj < 4; jj++) acc[jj] = b;
#pragma unroll 4
        for (int o = 0; o < FEAT; o++) {
            float wgt = Wo[o * FEAT + fo];
#pragma unroll
            for (int jj = 0; jj < 4; jj++)
                acc[jj] = fmaf(s_qp[(half * 4 + jj) * FEAT + o], wgt, acc[jj]);
        }
#pragma unroll
        for (int jj = 0; jj < 4; jj++) s_q[(half * 4 + jj) * FEAT + fo] = acc[jj];    // out (pre-LN)
    }
    __syncthreads();

    // ---- Phase G: LayerNorm + residual (warp w handles node j = w) ----
    {
        int j = w;
        int n = n0 + j;
        if (n < N) {
            float v0 = s_q[j * FEAT + lane];
            float v1 = s_q[j * FEAT + lane + 32];
            float v2 = s_q[j * FEAT + lane + 64];
            float v3 = s_q[j * FEAT + lane + 96];
            float mu = warp_sum(v0 + v1 + v2 + v3) * (1.f / FEAT);
            float d0 = v0 - mu, d1 = v1 - mu, d2 = v2 - mu, d3 = v3 - mu;
            float var = warp_sum(d0 * d0 + d1 * d1 + d2 * d2 + d3 * d3) * (1.f / FEAT);
            float rstd = rsqrtf(var + LN_EPS);
            size_t base = (size_t)n * FEAT;
            out[base + lane]      = query[base + lane]      + d0 * rstd * gamma[lane]      + beta[lane];
            out[base + lane + 32] = query[base + lane + 32] + d1 * rstd * gamma[lane + 32] + beta[lane + 32];
            out[base + lane + 64] = query[base + lane + 64] + d2 * rstd * gamma[lane + 64] + beta[lane + 64];
            out[base + lane + 96] = query[base + lane + 96] + d3 * rstd * gamma[lane + 96] + beta[lane + 96];
        }
    }
}

extern "C" void kernel_launch(void* const* d_in, const int* in_sizes, int n_in,
                              void* d_out, int out_size)
{
    const float* query = (const float*)d_in[0];
    const float* key   = (const float*)d_in[1];
    const float* value = (const float*)d_in[2];
    const int*   midx  = (const int*)d_in[3];
    const float* Wq = (const float*)d_in[4];  const float* bq = (const float*)d_in[5];
    const float* Wk = (const float*)d_in[6];  const float* bk = (const float*)d_in[7];
    const float* Wv = (const float*)d_in[8];  const float* bv = (const float*)d_in[9];
    const float* Wo = (const float*)d_in[10]; const float* bo = (const float*)d_in[11];
    const float* gamma = (const float*)d_in[12];
    const float* beta  = (const float*)d_in[13];

    int N = in_sizes[3];                    // element count of mask_idx = number of nodes
    int smem_bytes = SMEM_FLOATS * (int)sizeof(float);
    cudaFuncSetAttribute(mha_fused_kernel,
                         cudaFuncAttributeMaxDynamicSharedMemorySize, smem_bytes);
    int grid = (N + NB - 1) / NB;
    mha_fused_kernel<<<grid, THREADS, smem_bytes>>>(
        query, key, value, midx, Wq, bq, Wk, bk, Wv, bv, Wo, bo, gamma, beta,
        (float*)d_out, N);
}

// round 17
// speedup vs baseline: 1.2955x; 1.2955x over previous
#include <cuda_runtime.h>
#include <cstdint>
#include <math.h>

#define NB 8
#define THREADS 128
#define FEAT 128
#define SEQ 32
#define NHEAD 4
#define HDIM 32
#define LN_EPS 1e-5f
#define INV_SQRT_D 0.17677669529663687f

// dynamic smem layout (float offsets)
#define OFF_Q    0            // NB*128 query rows; reused as out rows (Phase F+)
#define OFF_QP   1024         // NB*128 qp; reused as attn [j][s*4+h]; reused as wv (Phase E)
#define OFF_T    2048         // NB*4*128 t vectors
#define OFF_KB0  6144         // 31*132=4092 (pad 4096): key buffer stage 0; u-dump overlay after loop
#define OFF_KB1  10240        // 4096: key buffer stage 1
#define OFF_VB   14336        // 32*132=4224: value buffer; also Wk stage [128][33] in Phase B
#define OFF_SB   18560        // NB*4 score bias
#define OFF_MI   18592        // NB mask values
#define SMEM_FLOATS 18624     // 74496 B -> 3 CTAs/SM (12 warps)

__device__ __forceinline__ float warp_max(float v) {
#pragma unroll
    for (int o = 16; o; o >>= 1) v = fmaxf(v, __shfl_xor_sync(0xffffffffu, v, o));
    return v;
}
__device__ __forceinline__ float warp_sum(float v) {
#pragma unroll
    for (int o = 16; o; o >>= 1) v += __shfl_xor_sync(0xffffffffu, v, o);
    return v;
}

// async-stage `rows` rows of a [SEQ, N, FEAT] tensor for node n into smem (stride 33 float4)
__device__ __forceinline__ void prefetch_rows(const float4* __restrict__ src4,
                                              uint32_t dst_smem_addr,
                                              int n, int rows, int N, int tid) {
    for (int r = tid; r < rows * 32; r += THREADS) {
        int s = r >> 5, k = r & 31;
        uint32_t dst = dst_smem_addr + (uint32_t)(s * 33 + k) * 16u;
        const float4* src = src4 + ((size_t)s * N + n) * 32 + k;
        asm volatile("cp.async.cg.shared.global [%0], [%1], 16;" :: "r"(dst), "l"(src));
    }
}

__global__ __launch_bounds__(THREADS)
void mha_fused_kernel(
    const float* __restrict__ query, const float* __restrict__ key,
    const float* __restrict__ value, const int* __restrict__ mask_idx,
    const float* __restrict__ Wq, const float* __restrict__ bq,
    const float* __restrict__ Wk, const float* __restrict__ bk,
    const float* __restrict__ Wv, const float* __restrict__ bv,
    const float* __restrict__ Wo, const float* __restrict__ bo,
    const float* __restrict__ gamma, const float* __restrict__ beta,
    float* __restrict__ out, int N)
{
    extern __shared__ float sm[];
    const int tid  = threadIdx.x;
    const int w    = tid >> 5;     // warp id == head id in score phase
    const int lane = tid & 31;
    const int n0   = blockIdx.x * NB;

    float* s_q    = sm + OFF_Q;
    float* s_qp   = sm + OFF_QP;   // -> attn -> wv
    float* s_t    = sm + OFF_T;
    float* s_vb   = sm + OFF_VB;   // V buffer; Wk staging during Phase B
    float* s_sb   = sm + OFF_SB;
    int*   s_mi   = (int*)(sm + OFF_MI);
    float* s_attn = s_qp;          // overlay (qp dead after sbias)
    float* s_uS   = sm + OFF_KB0;  // u dump overlay (K buffers dead after loop)

    const uint32_t kb_addr[2] = { (uint32_t)__cvta_generic_to_shared(sm + OFF_KB0),
                                  (uint32_t)__cvta_generic_to_shared(sm + OFF_KB1) };
    const uint32_t vb_addr = (uint32_t)__cvta_generic_to_shared(s_vb);
    const float4* key4 = reinterpret_cast<const float4*>(key);
    const float4* val4 = reinterpret_cast<const float4*>(value);

    // ---- stage query rows + mask values ----
#pragma unroll
    for (int j = 0; j < NB; j++) {
        int n = n0 + j;
        s_q[j * FEAT + tid] = (n < N) ? query[(size_t)n * FEAT + tid] : 0.f;
    }
    if (tid < NB) {
        int n = n0 + tid;
        s_mi[tid] = (n < N) ? mask_idx[n] : 0;
    }
    __syncthreads();

    // ---- prologue: issue K[0] into KB0 (covered by Phases A/B) ----
    {
        int m0 = s_mi[0];
        if (n0 < N && m0 > 0)              // m0==0 -> uniform attention, keys unused
            prefetch_rows(key4, kb_addr[0], n0, m0, N, tid);
        asm volatile("cp.async.commit_group;");
    }

    // ---- Phase A: qp = q @ Wq + bq  (thread = out feature, 8-node accumulators) ----
    {
        float acc[NB];
        float b = bq[tid];
#pragma unroll
        for (int j = 0; j < NB; j++) acc[j] = b;
#pragma unroll 4
        for (int f = 0; f < FEAT; f++) {
            float wgt = Wq[f * FEAT + tid];
#pragma unroll
            for (int j = 0; j < NB; j++) acc[j] = fmaf(s_q[j * FEAT + f], wgt, acc[j]);
        }
#pragma unroll
        for (int j = 0; j < NB; j++) s_qp[j * FEAT + tid] = acc[j];
    }
    __syncthreads();

    // ---- Phase B: t[j][h][f] = sum_d Wk[f, h*32+d] * qp[j, h*32+d] ----
    // Wk head chunk staged into the V buffer (V not prefetched until after Phase B).
    for (int h = 0; h < NHEAD; h++) {
        for (int r = tid; r < FEAT * HDIM; r += THREADS) {
            int f = r >> 5, dd = r & 31;
            s_vb[f * 33 + dd] = Wk[f * FEAT + h * HDIM + dd];
        }
        __syncthreads();
        float acc[NB];
#pragma unroll
        for (int j = 0; j < NB; j++) acc[j] = 0.f;
#pragma unroll
        for (int dd = 0; dd < HDIM; dd++) {
            float wgt = s_vb[tid * 33 + dd];
#pragma unroll
            for (int j = 0; j < NB; j++)
                acc[j] = fmaf(s_qp[j * FEAT + h * HDIM + dd], wgt, acc[j]);
        }
#pragma unroll
        for (int j = 0; j < NB; j++) s_t[j * (NHEAD * FEAT) + h * FEAT + tid] = acc[j];
        __syncthreads();
    }

    // ---- score bias: sbias[j][h] = qp_h . bk_h ----
    if (tid < NB * NHEAD) {
        int j = tid >> 2, h = tid & 3;
        float s = 0.f;
        for (int dd = 0; dd < HDIM; dd++)
            s += s_qp[j * FEAT + h * HDIM + dd] * bk[h * HDIM + dd];
        s_sb[tid] = s;
    }
    // s_sb + end-of-Wk-staging visibility established by the first bar in the loop.

    // ---- issue V[0] (covered by iter-0 scores; VB now free) ----
    {
        if (n0 < N) {
            int m0 = s_mi[0];
            int Sa0 = (m0 == 0) ? SEQ : m0;
            prefetch_rows(val4, vb_addr, n0, Sa0, N, tid);
        }
        asm volatile("cp.async.commit_group;");
    }

    // u accumulators live in registers across the fully-unrolled loop
    float ua0[NB], ua1[NB], ua2[NB], ua3[NB];

    // ---- Per-node loop: double-buffered K, single V ----
    // iter j: waitK | bar | issue K[j+1]->other buf | scores | waitV | bar | agg | bar | issue V[j+1]
#pragma unroll
    for (int j = 0; j < NB; j++) {
        const int p = j & 1;
        int n = n0 + j;
        bool valid = (n < N);
        int midx = valid ? s_mi[j] : 0;
        // midx==0: reference adds -1e9 which absorbs all scores in fp32 -> uniform softmax.
        bool uniform = (midx == 0);
        int Sa = uniform ? SEQ : midx;     // rows for V aggregation

        // ---- wait K[j] (leave newest group = V[j] in flight) ----
        asm volatile("cp.async.wait_group 1;" ::: "memory");
        __syncthreads();

        // ---- issue K[j+1] into the other K buffer (covered by rest of iter) ----
        if (j + 1 < NB) {
            int n2 = n0 + j + 1;
            if (n2 < N) {
                int m2 = s_mi[j + 1];
                if (m2 > 0) prefetch_rows(key4, kb_addr[1 - p], n2, m2, N, tid);
            }
        }
        asm volatile("cp.async.commit_group;");

        // ---- scores + softmax (warp = head, lane = seq pos) ----
        if (valid) {
            if (!uniform) {
                const float4* kb4 = reinterpret_cast<const float4*>(sm + (p ? OFF_KB1 : OFF_KB0));
                float sc = -1e30f;
                float pr = 0.f;
                if (lane < midx) {
                    const float4* t4 = reinterpret_cast<const float4*>(s_t + j * (NHEAD * FEAT) + w * FEAT);
                    float ax = 0.f, ay = 0.f, az = 0.f, aw = 0.f;
#pragma unroll 8
                    for (int k = 0; k < FEAT / 4; k++) {
                        float4 kv = kb4[lane * 33 + k];
                        float4 tv = t4[k];
                        ax = fmaf(kv.x, tv.x, ax);
                        ay = fmaf(kv.y, tv.y, ay);
                        az = fmaf(kv.z, tv.z, az);
                        aw = fmaf(kv.w, tv.w, aw);
                    }
                    sc = (((ax + ay) + (az + aw)) + s_sb[j * 4 + w]) * INV_SQRT_D;
                }
                float m = warp_max(sc);
                if (lane < midx) pr = expf(sc - m);
                float denom = warp_sum(pr);
                if (lane < midx) s_attn[j * FEAT + lane * 4 + w] = pr / denom;
            } else {
                s_attn[j * FEAT + lane * 4 + w] = 1.0f / SEQ;
            }
        }

        // ---- wait V[j] (K[j+1] group stays in flight); attn + V visible ----
        asm volatile("cp.async.wait_group 1;" ::: "memory");
        __syncthreads();

        // ---- agg: u[j][h][tid] = sum_{s<Sa} attn[s,h] * V_smem[s,tid] -> registers ----
        {
            const float* ab = s_attn + j * FEAT;
            float a0 = 0.f, a1 = 0.f, a2 = 0.f, a3 = 0.f;
#pragma unroll 8
            for (int s = 0; s < Sa; s++) {
                float vv = s_vb[s * 132 + tid];
                float4 av = *reinterpret_cast<const float4*>(ab + s * 4);
                a0 = fmaf(av.x, vv, a0);
                a1 = fmaf(av.y, vv, a1);
                a2 = fmaf(av.z, vv, a2);
                a3 = fmaf(av.w, vv, a3);
            }
            ua0[j] = a0; ua1[j] = a1; ua2[j] = a2; ua3[j] = a3;
        }
        __syncthreads();   // all agg reads of VB done before refill

        // ---- issue V[j+1] into VB (covered by next iter's waitK/bar/scores) ----
        if (j + 1 < NB) {
            int n2 = n0 + j + 1;
            if (n2 < N) {
                int m2 = s_mi[j + 1];
                int Sa2 = (m2 == 0) ? SEQ : m2;
                prefetch_rows(val4, vb_addr, n2, Sa2, N, tid);
            }
        }
        asm volatile("cp.async.commit_group;");
    }

    // ---- dump u registers into the dead K-buffer region ----
#pragma unroll
    for (int j = 0; j < NB; j++) {
        s_uS[j * (NHEAD * FEAT) + 0 * FEAT + tid] = ua0[j];
        s_uS[j * (NHEAD * FEAT) + 1 * FEAT + tid] = ua1[j];
        s_uS[j * (NHEAD * FEAT) + 2 * FEAT + tid] = ua2[j];
        s_uS[j * (NHEAD * FEAT) + 3 * FEAT + tid] = ua3[j];
    }
    __syncthreads();

    // ---- Phase E: wv[j][o] = bv[o] + sum_f u[j][o/32][f] * Wv[f,o]  (into s_qp overlay) ----
    {
        float acc[NB];
        float b = bv[tid];
#pragma unroll
        for (int j = 0; j < NB; j++) acc[j] = b;
        const int h = tid >> 5;
#pragma unroll 4
        for (int f = 0; f < FEAT; f++) {
            float wgt = Wv[f * FEAT + tid];
#pragma unroll
            for (int j = 0; j < NB; j++)
                acc[j] = fmaf(s_uS[j * (NHEAD * FEAT) + h * FEAT + f], wgt, acc[j]);
        }
#pragma unroll
        for (int j = 0; j < NB; j++) s_qp[j * FEAT + tid] = acc[j];   // wv
    }
    __syncthreads();

    // ---- Phase F: out[j][f'] = bo[f'] + sum_o wv[j][o] * Wo[o,f']  (into s_q overlay) ----
    {
        float acc[NB];
        float b = bo[tid];
#pragma unroll
        for (int j = 0; j < NB; j++) acc[j] = b;
#pragma unroll 4
        for (int o = 0; o < FEAT; o++) {
            float wgt = Wo[o * FEAT + tid];
#pragma unroll
            for (int j = 0; j < NB; j++)
                acc[j] = fmaf(s_qp[j * FEAT + o], wgt, acc[j]);
        }
#pragma unroll
        for (int j = 0; j < NB; j++) s_q[j * FEAT + tid] = acc[j];    // out (pre-LN)
    }
    __syncthreads();

    // ---- Phase G: LayerNorm + residual (warp handles nodes w, w+4) ----
    for (int j = w; j < NB; j += 4) {
        int n = n0 + j;
        if (n >= N) continue;
        float v0 = s_q[j * FEAT + lane];
        float v1 = s_q[j * FEAT + lane + 32];
        float v2 = s_q[j * FEAT + lane + 64];
        float v3 = s_q[j * FEAT + lane + 96];
        float mu = warp_sum(v0 + v1 + v2 + v3) * (1.f / FEAT);
        float d0 = v0 - mu, d1 = v1 - mu, d2 = v2 - mu, d3 = v3 - mu;
        float var = warp_sum(d0 * d0 + d1 * d1 + d2 * d2 + d3 * d3) * (1.f / FEAT);
        float rstd = rsqrtf(var + LN_EPS);
        size_t base = (size_t)n * FEAT;
        out[base + lane]      = query[base + lane]      + d0 * rstd * gamma[lane]      + beta[lane];
        out[base + lane + 32] = query[base + lane + 32] + d1 * rstd * gamma[lane + 32] + beta[lane + 32];
        out[base + lane + 64] = query[base + lane + 64] + d2 * rstd * gamma[lane + 64] + beta[lane + 64];
        out[base + lane + 96] = query[base + lane + 96] + d3 * rstd * gamma[lane + 96] + beta[lane + 96];
    }
}

extern "C" void kernel_launch(void* const* d_in, const int* in_sizes, int n_in,
                              void* d_out, int out_size)
{
    const float* query = (const float*)d_in[0];
    const float* key   = (const float*)d_in[1];
    const float* value = (const float*)d_in[2];
    const int*   midx  = (const int*)d_in[3];
    const float* Wq = (const float*)d_in[4];  const float* bq = (const float*)d_in[5];
    const float* Wk = (const float*)d_in[6];  const float* bk = (const float*)d_in[7];
    const float* Wv = (const float*)d_in[8];  const float* bv = (const float*)d_in[9];
    const float* Wo = (const float*)d_in[10]; const float* bo = (const float*)d_in[11];
    const float* gamma = (const float*)d_in[12];
    const float* beta  = (const float*)d_in[13];

    int N = in_sizes[3];                    // element count of mask_idx = number of nodes
    int smem_bytes = SMEM_FLOATS * (int)sizeof(float);
    cudaFuncSetAttribute(mha_fused_kernel,
                         cudaFuncAttributeMaxDynamicSharedMemorySize, smem_bytes);
    int grid = (N + NB - 1) / NB;
    mha_fused_kernel<<<grid, THREADS, smem_bytes>>>(
        query, key, value, midx, Wq, bq, Wk, bk, Wv, bv, Wo, bo, gamma, beta,
        (float*)d_out, N);
}